// round 1
// baseline (speedup 1.0000x reference)
#include <cuda_runtime.h>
#include <cstdint>

// Problem dims (fixed by the reference)
#define B_      4
#define S_      2048
#define D_      4096
#define O_      4096
#define M_      (B_ * S_)     // 8192 rows of the GEMM
#define TOPK_   2048
#define NMASKS_ 100

// Scratch (static device globals — no runtime allocation allowed)
__device__ float g_f[D_];
__device__ float g_mask[D_];                         // final mask as 0.0/1.0
__device__ __align__(16) float g_weff[(size_t)O_ * D_];  // 64 MB effective weight

// ---------------------------------------------------------------------------
// K1: f[d] = mean over rows 0..pb of x[0, :, d]
// ---------------------------------------------------------------------------
__global__ void mean_kernel(const float* __restrict__ x, const int* __restrict__ pb)
{
    int d = blockIdx.x * blockDim.x + threadIdx.x;
    int rows = pb[0] + 1;
    float s = 0.f;
    int r = 0;
    for (; r + 4 <= rows; r += 4) {
        s += x[(size_t)(r + 0) * D_ + d];
        s += x[(size_t)(r + 1) * D_ + d];
        s += x[(size_t)(r + 2) * D_ + d];
        s += x[(size_t)(r + 3) * D_ + d];
    }
    for (; r < rows; ++r) s += x[(size_t)r * D_ + d];
    g_f[d] = s / (float)rows;
}

// ---------------------------------------------------------------------------
// K2: top-k selection + permutation scatter + overlap/gate -> g_mask
// Single block, 1024 threads.
// ---------------------------------------------------------------------------
__global__ void select_kernel(const int* __restrict__ perm,
                              const unsigned char* __restrict__ stored)
{
    __shared__ unsigned int keys[D_];       // 16 KB
    __shared__ unsigned char amask[D_];     // 4 KB
    __shared__ int counts[NMASKS_];
    __shared__ int s_best[2];

    const int t = threadIdx.x;

    for (int j = t; j < D_; j += 1024) {
        keys[j]  = __float_as_uint(fabsf(g_f[j]));  // nonneg float -> order-preserving uint
        amask[j] = 0;
    }
    __syncthreads();

    // Exact top-k semantics: rank by (value desc, index asc). Distinct ranks
    // guarantee exactly TOPK_ selected.
    for (int j = t; j < D_; j += 1024) {
        const unsigned int kj = keys[j];
        int rank = 0;
        #pragma unroll 8
        for (int i = 0; i < D_; ++i) {
            unsigned int ki = keys[i];
            rank += (ki > kj) || (ki == kj && i < j);
        }
        if (rank < TOPK_) {
            amask[perm[j]] = 1;   // perm is a permutation -> no write conflicts
        }
    }
    __syncthreads();

    // Overlap counts: one warp per stored mask
    const int warp = t >> 5, lane = t & 31;
    for (int m = warp; m < NMASKS_; m += 32) {
        const unsigned char* row = stored + (size_t)m * D_;
        int c = 0;
        for (int d = lane; d < D_; d += 32)
            c += (int)(amask[d] & row[d]);
        #pragma unroll
        for (int o = 16; o > 0; o >>= 1) c += __shfl_down_sync(0xffffffffu, c, o);
        if (lane == 0) counts[m] = c;
    }
    __syncthreads();

    if (t == 0) {
        int best = -1, bi = 0;
        for (int m = 0; m < NMASKS_; ++m)
            if (counts[m] > best) { best = counts[m]; bi = m; }   // first max (jnp.argmax)
        s_best[0] = best;
        s_best[1] = bi;
    }
    __syncthreads();

    // gate: count/2048 >= float32(0.6)  <=>  count >= 1229 (no representable value between)
    const int gate = (s_best[0] >= 1229) ? 1 : 0;
    const unsigned char* brow = stored + (size_t)s_best[1] * D_;
    for (int d = t; d < D_; d += 1024)
        g_mask[d] = (gate && brow[d]) ? 1.0f : 0.0f;
}

// ---------------------------------------------------------------------------
// K3: W_eff[o,d] = W[o,d] + mask[d] * Wn[o,d]
// ---------------------------------------------------------------------------
__global__ void weff_kernel(const float* __restrict__ w, const float* __restrict__ wn)
{
    size_t i = (size_t)blockIdx.x * blockDim.x + threadIdx.x;   // float4 index
    const float4 a = ((const float4*)w)[i];
    const float4 b = ((const float4*)wn)[i];
    const int dbase = (int)((i * 4) & (size_t)(D_ - 1));
    float4 o;
    o.x = fmaf(g_mask[dbase + 0], b.x, a.x);
    o.y = fmaf(g_mask[dbase + 1], b.y, a.y);
    o.z = fmaf(g_mask[dbase + 2], b.z, a.z);
    o.w = fmaf(g_mask[dbase + 3], b.w, a.w);
    ((float4*)g_weff)[i] = o;
}

// ---------------------------------------------------------------------------
// K4: SGEMM  C[M,N] = X[M,K] * Weff[N,K]^T   (both K-major: NT layout)
// 128x128 block tile, BK=16, 256 threads, 8x8 per thread.
// ---------------------------------------------------------------------------
#define BM 128
#define BN 128
#define BK 16

__global__ __launch_bounds__(256, 2) void sgemm_kernel(
    const float* __restrict__ A,      // [M_, D_]
    float* __restrict__ C)            // [M_, O_]
{
    __shared__ float As[BK][BM];
    __shared__ float Bs[BK][BN];

    const float* Bmat = g_weff;

    const int bm  = blockIdx.y * BM;
    const int bn  = blockIdx.x * BN;
    const int tid = threadIdx.x;
    const int tx  = tid & 15;     // n direction (16)
    const int ty  = tid >> 4;     // m direction (16)

    const int lrow = tid >> 2;          // 0..63
    const int lk   = (tid & 3) * 4;     // 0,4,8,12

    const float* Aptr = A    + (size_t)bm * D_ + lk;
    const float* Bptr = Bmat + (size_t)bn * D_ + lk;

    float acc[8][8];
    #pragma unroll
    for (int i = 0; i < 8; ++i)
        #pragma unroll
        for (int j = 0; j < 8; ++j) acc[i][j] = 0.f;

    for (int k0 = 0; k0 < D_; k0 += BK) {
        #pragma unroll
        for (int h = 0; h < 2; ++h) {
            const int r = lrow + 64 * h;
            const float4 va = *(const float4*)(Aptr + (size_t)r * D_ + k0);
            const float4 vb = *(const float4*)(Bptr + (size_t)r * D_ + k0);
            As[lk + 0][r] = va.x;  As[lk + 1][r] = va.y;
            As[lk + 2][r] = va.z;  As[lk + 3][r] = va.w;
            Bs[lk + 0][r] = vb.x;  Bs[lk + 1][r] = vb.y;
            Bs[lk + 2][r] = vb.z;  Bs[lk + 3][r] = vb.w;
        }
        __syncthreads();

        #pragma unroll
        for (int k = 0; k < BK; ++k) {
            float a[8], b[8];
            *(float4*)&a[0] = *(const float4*)&As[k][ty * 8];
            *(float4*)&a[4] = *(const float4*)&As[k][ty * 8 + 4];
            *(float4*)&b[0] = *(const float4*)&Bs[k][tx * 8];
            *(float4*)&b[4] = *(const float4*)&Bs[k][tx * 8 + 4];
            #pragma unroll
            for (int i = 0; i < 8; ++i)
                #pragma unroll
                for (int j = 0; j < 8; ++j)
                    acc[i][j] = fmaf(a[i], b[j], acc[i][j]);
        }
        __syncthreads();
    }

    #pragma unroll
    for (int i = 0; i < 8; ++i) {
        float* crow = C + (size_t)(bm + ty * 8 + i) * O_ + bn + tx * 8;
        #pragma unroll
        for (int j = 0; j < 8; j += 4) {
            float4 v = make_float4(acc[i][j], acc[i][j+1], acc[i][j+2], acc[i][j+3]);
            *(float4*)(crow + j) = v;
        }
    }
}

// ---------------------------------------------------------------------------
extern "C" void kernel_launch(void* const* d_in, const int* in_sizes, int n_in,
                              void* d_out, int out_size)
{
    const float*         x      = (const float*)d_in[0];
    const float*         w      = (const float*)d_in[1];
    const float*         wn     = (const float*)d_in[2];
    const int*           perm   = (const int*)d_in[3];
    const unsigned char* stored = (const unsigned char*)d_in[4];
    const int*           pb     = (const int*)d_in[5];
    float*               out    = (float*)d_out;

    (void)in_sizes; (void)n_in; (void)out_size;

    mean_kernel<<<D_ / 256, 256>>>(x, pb);
    select_kernel<<<1, 1024>>>(perm, stored);

    const int weff_blocks = (int)(((size_t)O_ * D_ / 4) / 256);   // 16384
    weff_kernel<<<weff_blocks, 256>>>(w, wn);

    dim3 grid(O_ / BN, M_ / BM);   // (32, 64)
    sgemm_kernel<<<grid, 256>>>(x, out);
}

// round 3
// speedup vs baseline: 1.9501x; 1.9501x over previous
#include <cuda_runtime.h>
#include <cuda_bf16.h>
#include <cstdint>

// Problem dims (fixed by the reference)
#define B_      4
#define S_      2048
#define D_      4096
#define O_      4096
#define M_      8192
#define TOPK_   2048
#define NMASKS_ 100

// ---------------------------------------------------------------------------
// Static device scratch (no runtime allocation allowed)
// ---------------------------------------------------------------------------
__device__ float g_f[D_];
__device__ float g_mask[D_];
__device__ __align__(16) __nv_bfloat16 g_xhi[(size_t)M_ * D_];
__device__ __align__(16) __nv_bfloat16 g_xlo[(size_t)M_ * D_];
__device__ __align__(16) __nv_bfloat16 g_whi[(size_t)O_ * D_];
__device__ __align__(16) __nv_bfloat16 g_wlo[(size_t)O_ * D_];

// ---------------------------------------------------------------------------
// K1: f[d] = mean over rows 0..pb of x[0, :, d]
// ---------------------------------------------------------------------------
__global__ void mean_kernel(const float* __restrict__ x, const int* __restrict__ pb)
{
    int d = blockIdx.x * blockDim.x + threadIdx.x;
    int rows = pb[0] + 1;
    float s = 0.f;
    int r = 0;
    for (; r + 4 <= rows; r += 4) {
        s += x[(size_t)(r + 0) * D_ + d];
        s += x[(size_t)(r + 1) * D_ + d];
        s += x[(size_t)(r + 2) * D_ + d];
        s += x[(size_t)(r + 3) * D_ + d];
    }
    for (; r < rows; ++r) s += x[(size_t)r * D_ + d];
    g_f[d] = s / (float)rows;
}

// ---------------------------------------------------------------------------
// K2: top-k + permutation scatter + overlap/gate -> g_mask (single block)
// ---------------------------------------------------------------------------
__global__ void select_kernel(const int* __restrict__ perm,
                              const unsigned char* __restrict__ stored)
{
    __shared__ unsigned int keys[D_];
    __shared__ unsigned char amask[D_];
    __shared__ int counts[NMASKS_];
    __shared__ int s_best[2];

    const int t = threadIdx.x;

    for (int j = t; j < D_; j += 1024) {
        keys[j]  = __float_as_uint(fabsf(g_f[j]));
        amask[j] = 0;
    }
    __syncthreads();

    for (int j = t; j < D_; j += 1024) {
        const unsigned int kj = keys[j];
        int rank = 0;
        #pragma unroll 8
        for (int i = 0; i < D_; ++i) {
            unsigned int ki = keys[i];
            rank += (ki > kj) || (ki == kj && i < j);
        }
        if (rank < TOPK_) amask[perm[j]] = 1;
    }
    __syncthreads();

    const int warp = t >> 5, lane = t & 31;
    for (int m = warp; m < NMASKS_; m += 32) {
        const unsigned char* row = stored + (size_t)m * D_;
        int c = 0;
        for (int d = lane; d < D_; d += 32) c += (int)(amask[d] & row[d]);
        #pragma unroll
        for (int o = 16; o > 0; o >>= 1) c += __shfl_down_sync(0xffffffffu, c, o);
        if (lane == 0) counts[m] = c;
    }
    __syncthreads();

    if (t == 0) {
        int best = -1, bi = 0;
        for (int m = 0; m < NMASKS_; ++m)
            if (counts[m] > best) { best = counts[m]; bi = m; }
        s_best[0] = best; s_best[1] = bi;
    }
    __syncthreads();

    const int gate = (s_best[0] >= 1229) ? 1 : 0;   // count/2048 >= float32(0.6)
    const unsigned char* brow = stored + (size_t)s_best[1] * D_;
    for (int d = t; d < D_; d += 1024)
        g_mask[d] = (gate && brow[d]) ? 1.0f : 0.0f;
}

// ---------------------------------------------------------------------------
// K3a: split X into bf16 hi/lo   (8 elems/thread)
// ---------------------------------------------------------------------------
__global__ void split_x_kernel(const float* __restrict__ x)
{
    size_t i = ((size_t)blockIdx.x * 256 + threadIdx.x) * 8;
    float4 v0 = *(const float4*)(x + i);
    float4 v1 = *(const float4*)(x + i + 4);
    float v[8] = {v0.x, v0.y, v0.z, v0.w, v1.x, v1.y, v1.z, v1.w};
    __align__(16) __nv_bfloat16 h[8], l[8];
    #pragma unroll
    for (int j = 0; j < 8; ++j) {
        h[j] = __float2bfloat16(v[j]);
        l[j] = __float2bfloat16(v[j] - __bfloat162float(h[j]));
    }
    *(uint4*)(g_xhi + i) = *(uint4*)h;
    *(uint4*)(g_xlo + i) = *(uint4*)l;
}

// ---------------------------------------------------------------------------
// K3b: Weff = W + mask*Wn, split into bf16 hi/lo
// ---------------------------------------------------------------------------
__global__ void weff_split_kernel(const float* __restrict__ w,
                                  const float* __restrict__ wn)
{
    size_t i = ((size_t)blockIdx.x * 256 + threadIdx.x) * 8;
    const int dbase = (int)(i & (size_t)(D_ - 1));
    float4 w0 = *(const float4*)(w + i);
    float4 w1 = *(const float4*)(w + i + 4);
    float4 n0 = *(const float4*)(wn + i);
    float4 n1 = *(const float4*)(wn + i + 4);
    float wv[8] = {w0.x, w0.y, w0.z, w0.w, w1.x, w1.y, w1.z, w1.w};
    float nv[8] = {n0.x, n0.y, n0.z, n0.w, n1.x, n1.y, n1.z, n1.w};
    __align__(16) __nv_bfloat16 h[8], l[8];
    #pragma unroll
    for (int j = 0; j < 8; ++j) {
        float v = fmaf(g_mask[dbase + j], nv[j], wv[j]);
        h[j] = __float2bfloat16(v);
        l[j] = __float2bfloat16(v - __bfloat162float(h[j]));
    }
    *(uint4*)(g_whi + i) = *(uint4*)h;
    *(uint4*)(g_wlo + i) = *(uint4*)l;
}

// ---------------------------------------------------------------------------
// K4: bf16x3 GEMM via mma.sync (HMMA)  C[M,N] = X[M,K] * Weff[N,K]^T
//     128x128 CTA tile, 8 warps of 64x32, K-chunk 32, cp.async double buffer.
// ---------------------------------------------------------------------------
#define KC        32
#define NITER     (D_ / KC)      // 128
#define TSTRIDE   80             // bytes per smem row (32 bf16 + 8 pad), 16B aligned
#define TILE_B    (128 * TSTRIDE)        // 10240
#define T_AHI     0
#define T_ALO     (1 * TILE_B)
#define T_BHI     (2 * TILE_B)
#define T_BLO     (3 * TILE_B)
#define STAGE_B   (4 * TILE_B)           // 40960
#define SMEM_GEMM (2 * STAGE_B)          // 81920

__device__ __forceinline__ void ldsm_x4(uint32_t* r, uint32_t addr)
{
    asm volatile("ldmatrix.sync.aligned.m8n8.x4.shared.b16 {%0,%1,%2,%3}, [%4];"
                 : "=r"(r[0]), "=r"(r[1]), "=r"(r[2]), "=r"(r[3]) : "r"(addr));
}

__device__ __forceinline__ void mma16816(float* d, const uint32_t* a, const uint32_t* b)
{
    asm volatile("mma.sync.aligned.m16n8k16.row.col.f32.bf16.bf16.f32 "
                 "{%0,%1,%2,%3}, {%4,%5,%6,%7}, {%8,%9}, {%0,%1,%2,%3};"
                 : "+f"(d[0]), "+f"(d[1]), "+f"(d[2]), "+f"(d[3])
                 : "r"(a[0]), "r"(a[1]), "r"(a[2]), "r"(a[3]), "r"(b[0]), "r"(b[1]));
}

__device__ __forceinline__ void cp16(uint32_t dst, const void* src)
{
    asm volatile("cp.async.cg.shared.global [%0], [%1], 16;" :: "r"(dst), "l"(src));
}

__device__ __forceinline__ void stage_tile(uint32_t sdst, const __nv_bfloat16* __restrict__ src,
                                           int row0, int k0)
{
    const int tid = threadIdx.x;
    #pragma unroll
    for (int j = 0; j < 2; ++j) {
        int c   = tid + j * 256;        // 0..511
        int row = c >> 2;
        int col = c & 3;                // 16B chunk within 64B row payload
        cp16(sdst + row * TSTRIDE + col * 16,
             src + (size_t)(row0 + row) * D_ + k0 + col * 8);
    }
}

__device__ __forceinline__ void stage_all(uint32_t st, int bm, int bn, int k0)
{
    stage_tile(st + T_AHI, g_xhi, bm, k0);
    stage_tile(st + T_ALO, g_xlo, bm, k0);
    stage_tile(st + T_BHI, g_whi, bn, k0);
    stage_tile(st + T_BLO, g_wlo, bn, k0);
    asm volatile("cp.async.commit_group;" ::: "memory");
}

__global__ __launch_bounds__(256, 1) void gemm_kernel(float* __restrict__ C)
{
    extern __shared__ char smem[];
    uint32_t sbase;
    asm("{ .reg .u64 t; cvta.to.shared.u64 t, %1; cvt.u32.u64 %0, t; }"
        : "=r"(sbase) : "l"(smem));

    const int tid  = threadIdx.x;
    const int wid  = tid >> 5;
    const int lane = tid & 31;
    const int wm   = wid & 1;          // 2 warps along M
    const int wn   = wid >> 1;         // 4 warps along N
    const int bm   = blockIdx.y * 128;
    const int bn   = blockIdx.x * 128;

    float acc[4][4][4];
    #pragma unroll
    for (int i = 0; i < 4; ++i)
        #pragma unroll
        for (int j = 0; j < 4; ++j)
            #pragma unroll
            for (int e = 0; e < 4; ++e) acc[i][j][e] = 0.f;

    // lane addressing for ldmatrix (same formula for A and B tiles)
    const uint32_t lrow  = (uint32_t)(lane & 15);
    const uint32_t lkoff = (uint32_t)((lane >> 4) * 16);   // bytes: 8 bf16 half

    stage_all(sbase, bm, bn, 0);       // prologue: stage 0

    for (int it = 0; it < NITER; ++it) {
        const uint32_t st = sbase + (uint32_t)(it & 1) * STAGE_B;

        if (it + 1 < NITER) {
            stage_all(sbase + (uint32_t)((it + 1) & 1) * STAGE_B, bm, bn, (it + 1) * KC);
            asm volatile("cp.async.wait_group 1;" ::: "memory");
        } else {
            asm volatile("cp.async.wait_group 0;" ::: "memory");
        }
        __syncthreads();

        #pragma unroll
        for (int kk = 0; kk < KC; kk += 16) {
            const uint32_t kb = (uint32_t)(kk * 2) + lkoff;

            uint32_t ah[4][4], al[4][4];
            #pragma unroll
            for (int mt = 0; mt < 4; ++mt) {
                const uint32_t ro = (uint32_t)(wm * 64 + mt * 16) + lrow;
                ldsm_x4(ah[mt], st + T_AHI + ro * TSTRIDE + kb);
                ldsm_x4(al[mt], st + T_ALO + ro * TSTRIDE + kb);
            }

            uint32_t bh[4][2], bl[4][2];
            #pragma unroll
            for (int g = 0; g < 2; ++g) {
                const uint32_t ro = (uint32_t)(wn * 32 + g * 16) + lrow;
                uint32_t r[4];
                ldsm_x4(r, st + T_BHI + ro * TSTRIDE + kb);
                bh[2 * g][0]     = r[0]; bh[2 * g][1]     = r[2];
                bh[2 * g + 1][0] = r[1]; bh[2 * g + 1][1] = r[3];
                ldsm_x4(r, st + T_BLO + ro * TSTRIDE + kb);
                bl[2 * g][0]     = r[0]; bl[2 * g][1]     = r[2];
                bl[2 * g + 1][0] = r[1]; bl[2 * g + 1][1] = r[3];
            }

            #pragma unroll
            for (int mt = 0; mt < 4; ++mt)
                #pragma unroll
                for (int nt = 0; nt < 4; ++nt) {
                    mma16816(acc[mt][nt], ah[mt], bh[nt]);
                    mma16816(acc[mt][nt], ah[mt], bl[nt]);
                    mma16816(acc[mt][nt], al[mt], bh[nt]);
                }
        }
        __syncthreads();
    }

    // Epilogue: direct float2 stores
    const int er = lane >> 2;
    const int ec = (lane & 3) * 2;
    #pragma unroll
    for (int mt = 0; mt < 4; ++mt) {
        const int row = bm + wm * 64 + mt * 16 + er;
        #pragma unroll
        for (int nt = 0; nt < 4; ++nt) {
            const int col = bn + wn * 32 + nt * 8 + ec;
            *(float2*)(C + (size_t)row * O_ + col) =
                make_float2(acc[mt][nt][0], acc[mt][nt][1]);
            *(float2*)(C + (size_t)(row + 8) * O_ + col) =
                make_float2(acc[mt][nt][2], acc[mt][nt][3]);
        }
    }
}

// ---------------------------------------------------------------------------
extern "C" void kernel_launch(void* const* d_in, const int* in_sizes, int n_in,
                              void* d_out, int out_size)
{
    const float*         x      = (const float*)d_in[0];
    const float*         w      = (const float*)d_in[1];
    const float*         wn     = (const float*)d_in[2];
    const int*           perm   = (const int*)d_in[3];
    const unsigned char* stored = (const unsigned char*)d_in[4];
    const int*           pb     = (const int*)d_in[5];
    float*               out    = (float*)d_out;

    (void)in_sizes; (void)n_in; (void)out_size;

    static bool attr_set = false;
    if (!attr_set) {
        cudaFuncSetAttribute(gemm_kernel, cudaFuncAttributeMaxDynamicSharedMemorySize,
                             SMEM_GEMM);
        attr_set = true;
    }

    mean_kernel<<<D_ / 256, 256>>>(x, pb);
    select_kernel<<<1, 1024>>>(perm, stored);

    split_x_kernel<<<(int)(((size_t)M_ * D_ / 8) / 256), 256>>>(x);        // 16384 blocks
    weff_split_kernel<<<(int)(((size_t)O_ * D_ / 8) / 256), 256>>>(w, wn); // 8192 blocks

    dim3 grid(O_ / 128, M_ / 128);   // (32, 64)
    gemm_kernel<<<grid, 256, SMEM_GEMM>>>(out);
}

// round 4
// speedup vs baseline: 2.1935x; 1.1248x over previous
#include <cuda_runtime.h>
#include <cuda_bf16.h>
#include <cstdint>

// Problem dims (fixed by the reference)
#define B_      4
#define S_      2048
#define D_      4096
#define O_      4096
#define M_      8192
#define TOPK_   2048
#define NMASKS_ 100

// ---------------------------------------------------------------------------
// Static device scratch (no runtime allocation allowed)
// ---------------------------------------------------------------------------
__device__ float g_f[D_];
__device__ float g_mask[D_];
__device__ __align__(16) __nv_bfloat16 g_xhi[(size_t)M_ * D_];
__device__ __align__(16) __nv_bfloat16 g_xlo[(size_t)M_ * D_];
__device__ __align__(16) __nv_bfloat16 g_whi[(size_t)O_ * D_];
__device__ __align__(16) __nv_bfloat16 g_wlo[(size_t)O_ * D_];

// ---------------------------------------------------------------------------
// K1: f[d] = mean over rows 0..pb of x[0, :, d]
// ---------------------------------------------------------------------------
__global__ void mean_kernel(const float* __restrict__ x, const int* __restrict__ pb)
{
    int d = blockIdx.x * blockDim.x + threadIdx.x;
    int rows = pb[0] + 1;
    float s = 0.f;
    int r = 0;
    for (; r + 4 <= rows; r += 4) {
        s += x[(size_t)(r + 0) * D_ + d];
        s += x[(size_t)(r + 1) * D_ + d];
        s += x[(size_t)(r + 2) * D_ + d];
        s += x[(size_t)(r + 3) * D_ + d];
    }
    for (; r < rows; ++r) s += x[(size_t)r * D_ + d];
    g_f[d] = s / (float)rows;
}

// ---------------------------------------------------------------------------
// K2: top-k + permutation scatter + overlap/gate -> g_mask (single block)
// ---------------------------------------------------------------------------
__global__ void select_kernel(const int* __restrict__ perm,
                              const unsigned char* __restrict__ stored)
{
    __shared__ unsigned int keys[D_];
    __shared__ unsigned char amask[D_];
    __shared__ int counts[NMASKS_];
    __shared__ int s_best[2];

    const int t = threadIdx.x;

    for (int j = t; j < D_; j += 1024) {
        keys[j]  = __float_as_uint(fabsf(g_f[j]));
        amask[j] = 0;
    }
    __syncthreads();

    for (int j = t; j < D_; j += 1024) {
        const unsigned int kj = keys[j];
        int rank = 0;
        #pragma unroll 8
        for (int i = 0; i < D_; ++i) {
            unsigned int ki = keys[i];
            rank += (ki > kj) || (ki == kj && i < j);
        }
        if (rank < TOPK_) amask[perm[j]] = 1;
    }
    __syncthreads();

    const int warp = t >> 5, lane = t & 31;
    for (int m = warp; m < NMASKS_; m += 32) {
        const unsigned char* row = stored + (size_t)m * D_;
        int c = 0;
        for (int d = lane; d < D_; d += 32) c += (int)(amask[d] & row[d]);
        #pragma unroll
        for (int o = 16; o > 0; o >>= 1) c += __shfl_down_sync(0xffffffffu, c, o);
        if (lane == 0) counts[m] = c;
    }
    __syncthreads();

    if (t == 0) {
        int best = -1, bi = 0;
        for (int m = 0; m < NMASKS_; ++m)
            if (counts[m] > best) { best = counts[m]; bi = m; }
        s_best[0] = best; s_best[1] = bi;
    }
    __syncthreads();

    const int gate = (s_best[0] >= 1229) ? 1 : 0;   // count/2048 >= float32(0.6)
    const unsigned char* brow = stored + (size_t)s_best[1] * D_;
    for (int d = t; d < D_; d += 1024)
        g_mask[d] = (gate && brow[d]) ? 1.0f : 0.0f;
}

// ---------------------------------------------------------------------------
// K3a: split X into bf16 hi/lo   (8 elems/thread)
// ---------------------------------------------------------------------------
__global__ void split_x_kernel(const float* __restrict__ x)
{
    size_t i = ((size_t)blockIdx.x * 256 + threadIdx.x) * 8;
    float4 v0 = *(const float4*)(x + i);
    float4 v1 = *(const float4*)(x + i + 4);
    float v[8] = {v0.x, v0.y, v0.z, v0.w, v1.x, v1.y, v1.z, v1.w};
    __align__(16) __nv_bfloat16 h[8], l[8];
    #pragma unroll
    for (int j = 0; j < 8; ++j) {
        h[j] = __float2bfloat16(v[j]);
        l[j] = __float2bfloat16(v[j] - __bfloat162float(h[j]));
    }
    *(uint4*)(g_xhi + i) = *(uint4*)h;
    *(uint4*)(g_xlo + i) = *(uint4*)l;
}

// ---------------------------------------------------------------------------
// K3b: Weff = W + mask*Wn, split into bf16 hi/lo
// ---------------------------------------------------------------------------
__global__ void weff_split_kernel(const float* __restrict__ w,
                                  const float* __restrict__ wn)
{
    size_t i = ((size_t)blockIdx.x * 256 + threadIdx.x) * 8;
    const int dbase = (int)(i & (size_t)(D_ - 1));
    float4 w0 = *(const float4*)(w + i);
    float4 w1 = *(const float4*)(w + i + 4);
    float4 n0 = *(const float4*)(wn + i);
    float4 n1 = *(const float4*)(wn + i + 4);
    float wv[8] = {w0.x, w0.y, w0.z, w0.w, w1.x, w1.y, w1.z, w1.w};
    float nv[8] = {n0.x, n0.y, n0.z, n0.w, n1.x, n1.y, n1.z, n1.w};
    __align__(16) __nv_bfloat16 h[8], l[8];
    #pragma unroll
    for (int j = 0; j < 8; ++j) {
        float v = fmaf(g_mask[dbase + j], nv[j], wv[j]);
        h[j] = __float2bfloat16(v);
        l[j] = __float2bfloat16(v - __bfloat162float(h[j]));
    }
    *(uint4*)(g_whi + i) = *(uint4*)h;
    *(uint4*)(g_wlo + i) = *(uint4*)l;
}

// ---------------------------------------------------------------------------
// K4: bf16x3 GEMM via mma.sync (HMMA)  C[M,N] = X[M,K] * Weff[N,K]^T
//     128x128 CTA tile, 8 warps of 64x32, K-chunk 32, cp.async double buffer.
//     2 CTAs/SM for issue-latency hiding.
// ---------------------------------------------------------------------------
#define KC        32
#define NITER     (D_ / KC)      // 128
#define TSTRIDE   80             // bytes per smem row (32 bf16 + 8 pad), 16B aligned
#define TILE_B    (128 * TSTRIDE)        // 10240
#define T_AHI     0
#define T_ALO     (1 * TILE_B)
#define T_BHI     (2 * TILE_B)
#define T_BLO     (3 * TILE_B)
#define STAGE_B   (4 * TILE_B)           // 40960
#define SMEM_GEMM (2 * STAGE_B)          // 81920  (x2 CTAs = 160KB <= 228KB)

__device__ __forceinline__ void ldsm_x4(uint32_t* r, uint32_t addr)
{
    asm volatile("ldmatrix.sync.aligned.m8n8.x4.shared.b16 {%0,%1,%2,%3}, [%4];"
                 : "=r"(r[0]), "=r"(r[1]), "=r"(r[2]), "=r"(r[3]) : "r"(addr));
}

__device__ __forceinline__ void mma16816(float* d, const uint32_t* a, const uint32_t* b)
{
    asm volatile("mma.sync.aligned.m16n8k16.row.col.f32.bf16.bf16.f32 "
                 "{%0,%1,%2,%3}, {%4,%5,%6,%7}, {%8,%9}, {%0,%1,%2,%3};"
                 : "+f"(d[0]), "+f"(d[1]), "+f"(d[2]), "+f"(d[3])
                 : "r"(a[0]), "r"(a[1]), "r"(a[2]), "r"(a[3]), "r"(b[0]), "r"(b[1]));
}

__device__ __forceinline__ void cp16(uint32_t dst, const void* src)
{
    asm volatile("cp.async.cg.shared.global [%0], [%1], 16;" :: "r"(dst), "l"(src));
}

__device__ __forceinline__ void stage_tile(uint32_t sdst, const __nv_bfloat16* __restrict__ src,
                                           int row0, int k0)
{
    const int tid = threadIdx.x;
    #pragma unroll
    for (int j = 0; j < 2; ++j) {
        int c   = tid + j * 256;        // 0..511
        int row = c >> 2;
        int col = c & 3;                // 16B chunk within 64B row payload
        cp16(sdst + row * TSTRIDE + col * 16,
             src + (size_t)(row0 + row) * D_ + k0 + col * 8);
    }
}

__device__ __forceinline__ void stage_all(uint32_t st, int bm, int bn, int k0)
{
    stage_tile(st + T_AHI, g_xhi, bm, k0);
    stage_tile(st + T_ALO, g_xlo, bm, k0);
    stage_tile(st + T_BHI, g_whi, bn, k0);
    stage_tile(st + T_BLO, g_wlo, bn, k0);
    asm volatile("cp.async.commit_group;" ::: "memory");
}

__global__ __launch_bounds__(256, 2) void gemm_kernel(float* __restrict__ C)
{
    extern __shared__ char smem[];
    uint32_t sbase;
    asm("{ .reg .u64 t; cvta.to.shared.u64 t, %1; cvt.u32.u64 %0, t; }"
        : "=r"(sbase) : "l"(smem));

    const int tid  = threadIdx.x;
    const int wid  = tid >> 5;
    const int lane = tid & 31;
    const int wm   = wid & 1;          // 2 warps along M
    const int wn   = wid >> 1;         // 4 warps along N
    const int bm   = blockIdx.y * 128;
    const int bn   = blockIdx.x * 128;

    float acc[4][4][4];
    #pragma unroll
    for (int i = 0; i < 4; ++i)
        #pragma unroll
        for (int j = 0; j < 4; ++j)
            #pragma unroll
            for (int e = 0; e < 4; ++e) acc[i][j][e] = 0.f;

    // lane addressing for ldmatrix (same formula for A and B tiles)
    const uint32_t lrow  = (uint32_t)(lane & 15);
    const uint32_t lkoff = (uint32_t)((lane >> 4) * 16);   // bytes: 8 bf16 half

    stage_all(sbase, bm, bn, 0);       // prologue: stage 0

    for (int it = 0; it < NITER; ++it) {
        const uint32_t st = sbase + (uint32_t)(it & 1) * STAGE_B;

        if (it + 1 < NITER) {
            stage_all(sbase + (uint32_t)((it + 1) & 1) * STAGE_B, bm, bn, (it + 1) * KC);
            asm volatile("cp.async.wait_group 1;" ::: "memory");
        } else {
            asm volatile("cp.async.wait_group 0;" ::: "memory");
        }
        __syncthreads();

        #pragma unroll
        for (int kk = 0; kk < KC; kk += 16) {
            const uint32_t kb = (uint32_t)(kk * 2) + lkoff;

            // B fragments first (16 regs), then stream A rows (8 regs reused)
            uint32_t bh[4][2], bl[4][2];
            #pragma unroll
            for (int g = 0; g < 2; ++g) {
                const uint32_t ro = (uint32_t)(wn * 32 + g * 16) + lrow;
                uint32_t r[4];
                ldsm_x4(r, st + T_BHI + ro * TSTRIDE + kb);
                bh[2 * g][0]     = r[0]; bh[2 * g][1]     = r[2];
                bh[2 * g + 1][0] = r[1]; bh[2 * g + 1][1] = r[3];
                ldsm_x4(r, st + T_BLO + ro * TSTRIDE + kb);
                bl[2 * g][0]     = r[0]; bl[2 * g][1]     = r[2];
                bl[2 * g + 1][0] = r[1]; bl[2 * g + 1][1] = r[3];
            }

            #pragma unroll
            for (int mt = 0; mt < 4; ++mt) {
                const uint32_t ro = (uint32_t)(wm * 64 + mt * 16) + lrow;
                uint32_t ah[4], al[4];
                ldsm_x4(ah, st + T_AHI + ro * TSTRIDE + kb);
                ldsm_x4(al, st + T_ALO + ro * TSTRIDE + kb);
                #pragma unroll
                for (int nt = 0; nt < 4; ++nt) {
                    mma16816(acc[mt][nt], ah, bh[nt]);
                    mma16816(acc[mt][nt], ah, bl[nt]);
                    mma16816(acc[mt][nt], al, bh[nt]);
                }
            }
        }
        __syncthreads();
    }

    // Epilogue: direct float2 stores
    const int er = lane >> 2;
    const int ec = (lane & 3) * 2;
    #pragma unroll
    for (int mt = 0; mt < 4; ++mt) {
        const int row = bm + wm * 64 + mt * 16 + er;
        #pragma unroll
        for (int nt = 0; nt < 4; ++nt) {
            const int col = bn + wn * 32 + nt * 8 + ec;
            *(float2*)(C + (size_t)row * O_ + col) =
                make_float2(acc[mt][nt][0], acc[mt][nt][1]);
            *(float2*)(C + (size_t)(row + 8) * O_ + col) =
                make_float2(acc[mt][nt][2], acc[mt][nt][3]);
        }
    }
}

// ---------------------------------------------------------------------------
extern "C" void kernel_launch(void* const* d_in, const int* in_sizes, int n_in,
                              void* d_out, int out_size)
{
    const float*         x      = (const float*)d_in[0];
    const float*         w      = (const float*)d_in[1];
    const float*         wn     = (const float*)d_in[2];
    const int*           perm   = (const int*)d_in[3];
    const unsigned char* stored = (const unsigned char*)d_in[4];
    const int*           pb     = (const int*)d_in[5];
    float*               out    = (float*)d_out;

    (void)in_sizes; (void)n_in; (void)out_size;

    static bool attr_set = false;
    if (!attr_set) {
        cudaFuncSetAttribute(gemm_kernel, cudaFuncAttributeMaxDynamicSharedMemorySize,
                             SMEM_GEMM);
        attr_set = true;
    }

    mean_kernel<<<D_ / 256, 256>>>(x, pb);
    select_kernel<<<1, 1024>>>(perm, stored);

    split_x_kernel<<<(int)(((size_t)M_ * D_ / 8) / 256), 256>>>(x);        // 16384 blocks
    weff_split_kernel<<<(int)(((size_t)O_ * D_ / 8) / 256), 256>>>(w, wn); // 8192 blocks

    dim3 grid(O_ / 128, M_ / 128);   // (32, 64)
    gemm_kernel<<<grid, 256, SMEM_GEMM>>>(out);
}